// round 1
// baseline (speedup 1.0000x reference)
#include <cuda_runtime.h>
#include <math.h>

#define B 32
#define NTOK 4096
#define C 768
#define H 12
#define NSPLIT 16

// ---------------- scratch (no allocations allowed) ----------------
__device__ float g_q[B * C];                 // q, pre-scaled:  [b][h*64+d]
__device__ float g_t[B * C * H];             // t[b][c][h] = sum_d Wk[c, h*64+d] * q[b, h*64+d]
__device__ float g_s[B * NTOK * H];          // scores -> softmax weights, [b][n][h]
__device__ float g_yp[NSPLIT * B * H * C];   // split-K partials of y
__device__ float g_y[B * H * C];             // y[b][h][c] = sum_n w * x
__device__ float g_cls[B * C];               // cls flat [b][h*64+d]

// ---------------- K0a: q[b,j] = sum_c x[b,0,c] * Wq[c,j] * 0.125 ----------------
__global__ void k_q_kern(const float* __restrict__ x, const float* __restrict__ Wq) {
    int b = blockIdx.y, jj = blockIdx.x, tid = threadIdx.x;
    __shared__ float xs[C];
    const float* xr = x + (size_t)b * NTOK * C;   // token 0 row
    for (int i = tid; i < C; i += 256) xs[i] = xr[i];
    __syncthreads();
    int j = tid + jj * 256;
    float acc = 0.f;
    #pragma unroll 4
    for (int c = 0; c < C; c++) acc = fmaf(xs[c], Wq[c * C + j], acc);
    g_q[b * C + j] = acc * 0.125f;   // SCALE = 64^-0.5
}

// ---------------- K0b: t[b,c,h] = sum_d Wk[c, h*64+d] * q[b, h*64+d] ----------------
__global__ void k_t_kern(const float* __restrict__ Wkv) {
    int b = blockIdx.y, cc = blockIdx.x, tid = threadIdx.x;
    __shared__ float q_s[C];
    for (int i = tid; i < C; i += 256) q_s[i] = g_q[b * C + i];
    __syncthreads();
    int c = tid + cc * 256;
    const float* wr = Wkv + (size_t)c * (2 * C);   // K half: cols [0, C)
    float* tp = g_t + (size_t)b * C * H + c * H;
    #pragma unroll
    for (int h = 0; h < H; h++) {
        float a = 0.f;
        #pragma unroll
        for (int j4 = 0; j4 < 16; j4++) {
            float4 w = *(const float4*)(wr + h * 64 + j4 * 4);
            int j = h * 64 + j4 * 4;
            a = fmaf(w.x, q_s[j + 0], a);
            a = fmaf(w.y, q_s[j + 1], a);
            a = fmaf(w.z, q_s[j + 2], a);
            a = fmaf(w.w, q_s[j + 3], a);
        }
        tp[h] = a;
    }
}

// ---------------- K1: scores s[b,n,h] = sum_c x[b,n,c] * t[b,c,h] ----------------
// Skinny GEMM per (b, 256-token chunk). 128 threads, 2 tokens x 12 heads per thread.
__global__ void __launch_bounds__(128) k_score(const float* __restrict__ x) {
    __shared__ __align__(16) float x_s[32 * 256];   // [c_local][n]  (transposed tile)
    __shared__ __align__(16) float t_t[32 * H];     // [c_local][h]
    int b = blockIdx.y, n0 = blockIdx.x * 256, tid = threadIdx.x;
    const float* tb = g_t + (size_t)b * C * H;
    const float* xb = x + ((size_t)b * NTOK + n0) * C;

    float acc[2][H];
    #pragma unroll
    for (int i = 0; i < 2; i++)
        #pragma unroll
        for (int h = 0; h < H; h++) acc[i][h] = 0.f;

    for (int k0 = 0; k0 < C; k0 += 32) {
        __syncthreads();
        // stage t tile (coalesced)
        for (int i = tid; i < 32 * H; i += 128) t_t[i] = tb[k0 * H + i];
        // stage x tile transposed: 256 tokens x 32 c
        #pragma unroll
        for (int i = 0; i < 16; i++) {
            int idx = tid + i * 128;
            int n = idx & 255, c4 = idx >> 8;     // c4 in [0,8)
            float4 v = *(const float4*)(xb + (size_t)n * C + k0 + c4 * 4);
            x_s[(c4 * 4 + 0) * 256 + n] = v.x;
            x_s[(c4 * 4 + 1) * 256 + n] = v.y;
            x_s[(c4 * 4 + 2) * 256 + n] = v.z;
            x_s[(c4 * 4 + 3) * 256 + n] = v.w;
        }
        __syncthreads();
        #pragma unroll 8
        for (int c = 0; c < 32; c++) {
            float2 xv = *(const float2*)&x_s[c * 256 + tid * 2];
            float tt[H];
            *(float4*)&tt[0] = *(const float4*)&t_t[c * H + 0];
            *(float4*)&tt[4] = *(const float4*)&t_t[c * H + 4];
            *(float4*)&tt[8] = *(const float4*)&t_t[c * H + 8];
            #pragma unroll
            for (int h = 0; h < H; h++) {
                acc[0][h] = fmaf(xv.x, tt[h], acc[0][h]);
                acc[1][h] = fmaf(xv.y, tt[h], acc[1][h]);
            }
        }
    }
    #pragma unroll
    for (int i = 0; i < 2; i++) {
        int n = n0 + tid * 2 + i;
        float* sp = g_s + ((size_t)b * NTOK + n) * H;
        ((float4*)sp)[0] = make_float4(acc[i][0], acc[i][1], acc[i][2], acc[i][3]);
        ((float4*)sp)[1] = make_float4(acc[i][4], acc[i][5], acc[i][6], acc[i][7]);
        ((float4*)sp)[2] = make_float4(acc[i][8], acc[i][9], acc[i][10], acc[i][11]);
    }
}

// ---------------- K2: softmax over n for each (b,h); in place s -> w ----------------
__global__ void k_softmax() {
    int b = blockIdx.x, tid = threadIdx.x;
    int w = tid >> 5, lane = tid & 31;   // 12 warps, warp = head
    __shared__ __align__(16) float tile[512 * H];
    __shared__ float m_s[H], li_s[H];
    float* sb = g_s + (size_t)b * NTOK * H;

    float mx = -1e30f;
    for (int t0 = 0; t0 < NTOK; t0 += 512) {
        __syncthreads();
        for (int i = tid; i < 512 * H; i += 384) tile[i] = sb[(size_t)t0 * H + i];
        __syncthreads();
        #pragma unroll
        for (int k = 0; k < 16; k++) mx = fmaxf(mx, tile[(lane + k * 32) * H + w]);
    }
    #pragma unroll
    for (int o = 16; o; o >>= 1) mx = fmaxf(mx, __shfl_xor_sync(0xffffffffu, mx, o));

    float sum = 0.f;
    for (int t0 = 0; t0 < NTOK; t0 += 512) {
        __syncthreads();
        for (int i = tid; i < 512 * H; i += 384) tile[i] = sb[(size_t)t0 * H + i];
        __syncthreads();
        #pragma unroll
        for (int k = 0; k < 16; k++) sum += __expf(tile[(lane + k * 32) * H + w] - mx);
    }
    #pragma unroll
    for (int o = 16; o; o >>= 1) sum += __shfl_xor_sync(0xffffffffu, sum, o);

    if (lane == 0) { m_s[w] = mx; li_s[w] = 1.f / sum; }
    __syncthreads();
    // pass 3: coalesced rewrite  w = exp(s - m) / l
    for (int i = tid; i < NTOK * H; i += 384) {
        int h = i % H;
        sb[i] = __expf(sb[i] - m_s[h]) * li_s[h];
    }
}

// ---------------- K3: y partial: yp[split,b,h,c] = sum_{n in split} w[b,n,h] * x[b,n,c] ----------------
__global__ void __launch_bounds__(128) k_y(const float* __restrict__ x) {
    __shared__ __align__(16) float w_s[256 * H];
    int b = blockIdx.y, split = blockIdx.x, tid = threadIdx.x;
    int n0 = split * 256;
    const float* wb = g_s + ((size_t)b * NTOK + n0) * H;
    for (int i = tid; i < 256 * H; i += 128) w_s[i] = wb[i];
    __syncthreads();

    float acc[H][6];
    #pragma unroll
    for (int h = 0; h < H; h++)
        #pragma unroll
        for (int cb = 0; cb < 6; cb++) acc[h][cb] = 0.f;

    const float* xb = x + ((size_t)b * NTOK + n0) * C;
    #pragma unroll 2
    for (int n = 0; n < 256; n++) {
        const float* xr = xb + (size_t)n * C;
        float xv[6];
        #pragma unroll
        for (int cb = 0; cb < 6; cb++) xv[cb] = xr[tid + cb * 128];
        float ww[H];
        *(float4*)&ww[0] = *(const float4*)&w_s[n * H + 0];
        *(float4*)&ww[4] = *(const float4*)&w_s[n * H + 4];
        *(float4*)&ww[8] = *(const float4*)&w_s[n * H + 8];
        #pragma unroll
        for (int h = 0; h < H; h++)
            #pragma unroll
            for (int cb = 0; cb < 6; cb++)
                acc[h][cb] = fmaf(ww[h], xv[cb], acc[h][cb]);
    }
    float* yp = g_yp + ((size_t)split * B + b) * H * C;
    #pragma unroll
    for (int h = 0; h < H; h++)
        #pragma unroll
        for (int cb = 0; cb < 6; cb++)
            yp[h * C + tid + cb * 128] = acc[h][cb];
}

// ---------------- K3b: reduce splits ----------------
__global__ void k_yred() {
    int gi = blockIdx.x * 256 + threadIdx.x;   // < B*H*C
    float s = 0.f;
    #pragma unroll
    for (int sp = 0; sp < NSPLIT; sp++) s += g_yp[(size_t)sp * B * H * C + gi];
    g_y[gi] = s;
}

// ---------------- K4a: cls[b, h*64+d] = sum_c y[b,h,c] * Wv[c, h*64+d] ----------------
__global__ void k_cls(const float* __restrict__ Wkv) {
    int b = blockIdx.y, jj = blockIdx.x, tid = threadIdx.x;
    __shared__ float y_s[H * C];
    for (int i = tid; i < H * C; i += 256) y_s[i] = g_y[(size_t)b * H * C + i];
    __syncthreads();
    int j = tid + jj * 256;
    int h = j >> 6;
    const float* ys = &y_s[h * C];
    float acc = 0.f;
    #pragma unroll 4
    for (int c = 0; c < C; c++)
        acc = fmaf(ys[c], Wkv[(size_t)c * (2 * C) + C + j], acc);   // V half
    g_cls[b * C + j] = acc;
}

// ---------------- K4b: out[b,j] = bp[j] + sum_i cls[b,i] * Wp[i,j] ----------------
__global__ void k_out(const float* __restrict__ Wp, const float* __restrict__ bp,
                      float* __restrict__ out) {
    int b = blockIdx.y, jj = blockIdx.x, tid = threadIdx.x;
    __shared__ float c_s[C];
    for (int i = tid; i < C; i += 256) c_s[i] = g_cls[b * C + i];
    __syncthreads();
    int j = tid + jj * 256;
    float acc = bp[j];
    #pragma unroll 4
    for (int c = 0; c < C; c++) acc = fmaf(c_s[c], Wp[(size_t)c * C + j], acc);
    out[b * C + j] = acc;
}

// ---------------- launcher ----------------
extern "C" void kernel_launch(void* const* d_in, const int* in_sizes, int n_in,
                              void* d_out, int out_size) {
    const float* x   = (const float*)d_in[0];
    const float* Wq  = (const float*)d_in[1];
    const float* Wkv = (const float*)d_in[2];
    const float* Wp  = (const float*)d_in[3];
    const float* bp  = (const float*)d_in[4];
    float* out = (float*)d_out;

    k_q_kern <<<dim3(3, B), 256>>>(x, Wq);
    k_t_kern <<<dim3(3, B), 256>>>(Wkv);
    k_score  <<<dim3(NTOK / 256, B), 128>>>(x);
    k_softmax<<<B, 384>>>();
    k_y      <<<dim3(NSPLIT, B), 128>>>(x);
    k_yred   <<<(B * H * C) / 256, 256>>>();
    k_cls    <<<dim3(3, B), 256>>>(Wkv);
    k_out    <<<dim3(3, B), 256>>>(Wp, bp, out);
}

// round 3
// speedup vs baseline: 1.5309x; 1.5309x over previous
#include <cuda_runtime.h>
#include <math.h>

#define B 32
#define NTOK 4096
#define C 768
#define H 12
#define CH 8            // chunks per batch
#define CHTOK 512       // tokens per chunk
#define XS_STRIDE 516   // padded row stride (floats) for transposed x tile

// ---------------- scratch ----------------
__device__ float g_q[B * C];               // pre-scaled q [b][h*64+d]
__device__ float g_t[B * C * H];           // t[b][c][h] = Wk[c,hd] . q[b,hd]
__device__ float g_cm[B * CH * H];         // chunk max
__device__ float g_cl[B * CH * H];         // chunk expsum (rel. chunk max)
__device__ float g_scale[B * CH * H];      // e^{m_c - M} / L
__device__ float g_yp[CH * B * H * C];     // chunk-partial y (unnormalized)
__device__ float g_y[B * H * C];
__device__ float g_cls[B * C];

// ---------------- f32x2 helpers ----------------
#define FMA2(d, a, b) asm("fma.rn.f32x2 %0, %1, %2, %0;" : "+l"(d) : "l"(a), "l"(b))

__device__ __forceinline__ unsigned long long dup2(float v) {
    unsigned int u = __float_as_uint(v);
    return ((unsigned long long)u << 32) | (unsigned long long)u;
}
__device__ __forceinline__ float2 unpk(unsigned long long p) {
    float2 r;
    r.x = __uint_as_float((unsigned int)p);
    r.y = __uint_as_float((unsigned int)(p >> 32));
    return r;
}

// ---------------- K0a: q[b,j] = (x[b,0,:] @ Wq)[j] * 0.125 ----------------
__global__ void k_q_kern(const float* __restrict__ x, const float* __restrict__ Wq) {
    int b = blockIdx.y, jj = blockIdx.x, tid = threadIdx.x;
    __shared__ float xs[C];
    const float* xr = x + (size_t)b * NTOK * C;
    for (int i = tid; i < C; i += 256) xs[i] = xr[i];
    __syncthreads();
    int j = tid + jj * 256;
    float a0 = 0.f, a1 = 0.f;
    #pragma unroll 8
    for (int c = 0; c < C; c += 2) {
        a0 = fmaf(xs[c],     Wq[(size_t)c * C + j],       a0);
        a1 = fmaf(xs[c + 1], Wq[(size_t)(c + 1) * C + j], a1);
    }
    g_q[b * C + j] = (a0 + a1) * 0.125f;
}

// ---------------- K0b: t[b,c,h] = sum_d Wk[c,h*64+d] * q[b,h*64+d] ----------------
#define TROWS 12
__global__ void k_t_kern(const float* __restrict__ Wkv) {
    __shared__ float wk[TROWS * C];
    __shared__ float qs[C];
    int b = blockIdx.y, c0 = blockIdx.x * TROWS, tid = threadIdx.x;  // 144 threads
    for (int i = tid; i < C; i += 144) qs[i] = g_q[b * C + i];
    for (int i = tid; i < TROWS * C; i += 144)
        wk[i] = Wkv[(size_t)(c0 + i / C) * (2 * C) + (i % C)];
    __syncthreads();
    int cl = tid / 12, h = tid % 12;
    float a0 = 0.f, a1 = 0.f, a2 = 0.f, a3 = 0.f;
    #pragma unroll
    for (int j = 0; j < 16; j++) {
        int d4 = ((j + h) & 15) * 4;     // rotate to spread banks
        float4 w = *(const float4*)&wk[cl * C + h * 64 + d4];
        float4 q4 = *(const float4*)&qs[h * 64 + d4];
        a0 = fmaf(w.x, q4.x, a0); a1 = fmaf(w.y, q4.y, a1);
        a2 = fmaf(w.z, q4.z, a2); a3 = fmaf(w.w, q4.w, a3);
    }
    g_t[(size_t)b * C * H + (size_t)(c0 + cl) * H + h] = (a0 + a1) + (a2 + a3);
}

// ---------------- K1 fused: scores + chunk softmax stats + unnormalized y partial ----------------
// grid (CH, B), 128 threads. Each thread: 4 tokens (score phase), 6 c-columns (y phase).
__global__ void __launch_bounds__(128) k_fused(const float* __restrict__ x) {
    extern __shared__ __align__(16) char dynbuf[];
    float* xs = (float*)dynbuf;                                        // 32 x 516 floats (phase1)
    unsigned long long* w2s = (unsigned long long*)dynbuf;             // 512 x 12 u64 (phase2, alias)
    unsigned long long* t2s = (unsigned long long*)(dynbuf + 66048);   // 32 x 12 u64
    float* redm = (float*)(dynbuf + 66048 + 3072);                     // 4 x 12
    float* redl = redm + 48;                                           // 4 x 12

    int b = blockIdx.y, ch = blockIdx.x, tid = threadIdx.x;
    int wid = tid >> 5, lane = tid & 31;
    const float* xb = x + ((size_t)b * NTOK + (size_t)ch * CHTOK) * C;
    const float* tb = g_t + (size_t)b * C * H;

    // ---- phase 1: scores for 512 tokens x 12 heads ----
    unsigned long long acc0[H], acc1[H];   // tokens {4t,4t+1} and {4t+2,4t+3}
    #pragma unroll
    for (int h = 0; h < H; h++) { acc0[h] = 0ull; acc1[h] = 0ull; }

    for (int k0 = 0; k0 < C; k0 += 32) {
        __syncthreads();
        // stage t tile duplicated into both f32x2 lanes (coalesced gmem read)
        for (int i = tid; i < 32 * H; i += 128) t2s[i] = dup2(tb[(size_t)k0 * H + i]);
        // stage x tile transposed, coalesced: warp covers 4 full 128B rows per LDG.128
        #pragma unroll
        for (int j = 0; j < 32; j++) {
            int idx = tid + j * 128;
            int n = idx >> 3, c8 = (idx & 7) * 4;
            float4 v = *(const float4*)(xb + (size_t)n * C + k0 + c8);
            xs[(c8 + 0) * XS_STRIDE + n] = v.x;
            xs[(c8 + 1) * XS_STRIDE + n] = v.y;
            xs[(c8 + 2) * XS_STRIDE + n] = v.z;
            xs[(c8 + 3) * XS_STRIDE + n] = v.w;
        }
        __syncthreads();
        #pragma unroll
        for (int c = 0; c < 32; c++) {
            ulonglong2 xp = *(const ulonglong2*)&xs[c * XS_STRIDE + tid * 4];
            #pragma unroll
            for (int p = 0; p < 6; p++) {
                ulonglong2 tt = *(const ulonglong2*)&t2s[c * 12 + p * 2];
                FMA2(acc0[p * 2],     xp.x, tt.x);
                FMA2(acc1[p * 2],     xp.y, tt.x);
                FMA2(acc0[p * 2 + 1], xp.x, tt.y);
                FMA2(acc1[p * 2 + 1], xp.y, tt.y);
            }
        }
    }
    __syncthreads();   // all xs reads done before w2s overlays it

    // ---- chunk softmax stats ----
    float m[H];
    #pragma unroll
    for (int h = 0; h < H; h++) {
        float2 a = unpk(acc0[h]), c2 = unpk(acc1[h]);
        m[h] = fmaxf(fmaxf(a.x, a.y), fmaxf(c2.x, c2.y));
    }
    #pragma unroll
    for (int o = 16; o; o >>= 1) {
        #pragma unroll
        for (int h = 0; h < H; h++) m[h] = fmaxf(m[h], __shfl_xor_sync(0xffffffffu, m[h], o));
    }
    if (!lane) {
        for (int h = 0; h < H; h++) redm[wid * 12 + h] = m[h];
    }
    __syncthreads();
    #pragma unroll
    for (int h = 0; h < H; h++)
        m[h] = fmaxf(fmaxf(redm[h], redm[12 + h]), fmaxf(redm[24 + h], redm[36 + h]));

    // exp weights (unnormalized, rel. chunk max), duplicated into smem; local expsum
    float l[H];
    #pragma unroll
    for (int h = 0; h < H; h++) {
        float2 a = unpk(acc0[h]), c2 = unpk(acc1[h]);
        float e0 = __expf(a.x - m[h]),  e1 = __expf(a.y - m[h]);
        float e2 = __expf(c2.x - m[h]), e3 = __expf(c2.y - m[h]);
        w2s[(size_t)(tid * 4 + 0) * 12 + h] = dup2(e0);
        w2s[(size_t)(tid * 4 + 1) * 12 + h] = dup2(e1);
        w2s[(size_t)(tid * 4 + 2) * 12 + h] = dup2(e2);
        w2s[(size_t)(tid * 4 + 3) * 12 + h] = dup2(e3);
        l[h] = (e0 + e1) + (e2 + e3);
    }
    #pragma unroll
    for (int o = 16; o; o >>= 1) {
        #pragma unroll
        for (int h = 0; h < H; h++) l[h] += __shfl_xor_sync(0xffffffffu, l[h], o);
    }
    if (!lane) {
        for (int h = 0; h < H; h++) redl[wid * 12 + h] = l[h];
    }
    __syncthreads();
    if (tid == 0) {
        #pragma unroll
        for (int h = 0; h < H; h++) {
            g_cm[((size_t)b * CH + ch) * H + h] = m[h];
            g_cl[((size_t)b * CH + ch) * H + h] =
                ((redl[h] + redl[12 + h]) + (redl[24 + h] + redl[36 + h]));
        }
    }

    // ---- phase 2: y partial = sum_n w[n,h] * x[n,c]  (x re-read, mostly L2) ----
    unsigned long long ya[H][3];
    #pragma unroll
    for (int h = 0; h < H; h++) {
        #pragma unroll
        for (int p = 0; p < 3; p++) ya[h][p] = 0ull;
    }

    #pragma unroll 1
    for (int n0 = 0; n0 < CHTOK; n0 += 4) {
        unsigned long long xv[4][3];
        #pragma unroll
        for (int j = 0; j < 4; j++) {
            #pragma unroll
            for (int p = 0; p < 3; p++)
                xv[j][p] = *(const unsigned long long*)(xb + (size_t)(n0 + j) * C + tid * 2 + p * 256);
        }
        #pragma unroll
        for (int j = 0; j < 4; j++) {
            const unsigned long long* wr = &w2s[(size_t)(n0 + j) * 12];
            #pragma unroll
            for (int q = 0; q < 6; q++) {
                ulonglong2 wp = *(const ulonglong2*)&wr[q * 2];
                FMA2(ya[q * 2][0],     xv[j][0], wp.x);
                FMA2(ya[q * 2][1],     xv[j][1], wp.x);
                FMA2(ya[q * 2][2],     xv[j][2], wp.x);
                FMA2(ya[q * 2 + 1][0], xv[j][0], wp.y);
                FMA2(ya[q * 2 + 1][1], xv[j][1], wp.y);
                FMA2(ya[q * 2 + 1][2], xv[j][2], wp.y);
            }
        }
    }
    float* yp = g_yp + ((size_t)ch * B + b) * H * C;
    #pragma unroll
    for (int h = 0; h < H; h++) {
        #pragma unroll
        for (int p = 0; p < 3; p++)
            *(unsigned long long*)(yp + (size_t)h * C + tid * 2 + p * 256) = ya[h][p];
    }
}

// ---------------- K2: finalize softmax stats ----------------
__global__ void k_stats() {
    int b = blockIdx.x, h = threadIdx.x;
    if (h >= H) return;
    float m = -1e30f;
    #pragma unroll
    for (int ch = 0; ch < CH; ch++) m = fmaxf(m, g_cm[((size_t)b * CH + ch) * H + h]);
    float L = 0.f;
    #pragma unroll
    for (int ch = 0; ch < CH; ch++)
        L += g_cl[((size_t)b * CH + ch) * H + h] * __expf(g_cm[((size_t)b * CH + ch) * H + h] - m);
    float Li = 1.f / L;
    #pragma unroll
    for (int ch = 0; ch < CH; ch++)
        g_scale[((size_t)b * CH + ch) * H + h] =
            __expf(g_cm[((size_t)b * CH + ch) * H + h] - m) * Li;
}

// ---------------- K3: scaled reduce of y partials ----------------
__global__ void k_yred() {
    int gi = blockIdx.x * 256 + threadIdx.x;        // < B*H*C
    int c = gi % C, bh = gi / C;
    int h = bh % H, b = bh / H;
    float s = 0.f;
    #pragma unroll
    for (int ch = 0; ch < CH; ch++)
        s += g_yp[(((size_t)ch * B + b) * H + h) * C + c] * g_scale[((size_t)b * CH + ch) * H + h];
    g_y[gi] = s;
}

// ---------------- K4a: cls[b,j] = y[b, j>>6, :] . Wv[:, j] ----------------
__global__ void k_cls(const float* __restrict__ Wkv) {
    int b = blockIdx.y, jj = blockIdx.x, tid = threadIdx.x;
    __shared__ float y_s[H * C];
    for (int i = tid; i < H * C; i += 256) y_s[i] = g_y[(size_t)b * H * C + i];
    __syncthreads();
    int j = tid + jj * 256;
    const float* ys = &y_s[(j >> 6) * C];
    float a0 = 0.f, a1 = 0.f;
    #pragma unroll 8
    for (int c = 0; c < C; c += 2) {
        a0 = fmaf(ys[c],     Wkv[(size_t)c * (2 * C) + C + j],       a0);
        a1 = fmaf(ys[c + 1], Wkv[(size_t)(c + 1) * (2 * C) + C + j], a1);
    }
    g_cls[b * C + j] = a0 + a1;
}

// ---------------- K4b: out = cls @ Wp + bp ----------------
__global__ void k_out(const float* __restrict__ Wp, const float* __restrict__ bp,
                      float* __restrict__ out) {
    int b = blockIdx.y, jj = blockIdx.x, tid = threadIdx.x;
    __shared__ float c_s[C];
    for (int i = tid; i < C; i += 256) c_s[i] = g_cls[b * C + i];
    __syncthreads();
    int j = tid + jj * 256;
    float a0 = bp[j], a1 = 0.f;
    #pragma unroll 8
    for (int c = 0; c < C; c += 2) {
        a0 = fmaf(c_s[c],     Wp[(size_t)c * C + j],       a0);
        a1 = fmaf(c_s[c + 1], Wp[(size_t)(c + 1) * C + j], a1);
    }
    out[b * C + j] = a0 + a1;
}

// ---------------- launcher ----------------
extern "C" void kernel_launch(void* const* d_in, const int* in_sizes, int n_in,
                              void* d_out, int out_size) {
    const float* x   = (const float*)d_in[0];
    const float* Wq  = (const float*)d_in[1];
    const float* Wkv = (const float*)d_in[2];
    const float* Wp  = (const float*)d_in[3];
    const float* bp  = (const float*)d_in[4];
    float* out = (float*)d_out;

    const int FUSED_SMEM = 66048 + 3072 + 384;   // xs/w2s union + t2s + reductions
    cudaFuncSetAttribute(k_fused, cudaFuncAttributeMaxDynamicSharedMemorySize, FUSED_SMEM);

    k_q_kern<<<dim3(3, B), 256>>>(x, Wq);
    k_t_kern<<<dim3(C / TROWS, B), 144>>>(Wkv);
    k_fused <<<dim3(CH, B), 128, FUSED_SMEM>>>(x);
    k_stats <<<B, 32>>>();
    k_yred  <<<(B * H * C) / 256, 256>>>();
    k_cls   <<<dim3(3, B), 256>>>(Wkv);
    k_out   <<<dim3(3, B), 256>>>(Wp, bp, out);
}